// round 5
// baseline (speedup 1.0000x reference)
#include <cuda_runtime.h>
#include <cuda_bf16.h>
#include <math.h>
#include <stdint.h>

typedef unsigned long long u64;
typedef __nv_bfloat16 bf16;

#define BB 2
#define SS 1024
#define HID 3072
#define NH 16
#define QL 1536
#define KVL 512
#define NOPEd 128
#define ROPEd 64
#define QKD 192
#define VHD 128
#define NT (BB*SS)
#define KVOUT 256
#define KVA_N 576          /* KVL + ROPE */
#define KVA_NP 640         /* padded to multiple of 128 */
#define SCALE 0.07216878364870323f

// ------------------------------------------------------------------
// scratch (device globals)
// ------------------------------------------------------------------
#define AL __align__(256)
__device__ AL bf16  g_hs_h [NT*HID],      g_hs_l [NT*HID];
__device__ AL bf16  g_wqa_h[QL*HID],      g_wqa_l[QL*HID];
__device__ AL bf16  g_wqb_h[HID*QL],      g_wqb_l[HID*QL];
__device__ AL bf16  g_wkva_h[KVA_NP*HID], g_wkva_l[KVA_NP*HID];
__device__ AL bf16  g_wkvb_h[NH*KVOUT*KVL], g_wkvb_l[NH*KVOUT*KVL];
__device__ AL bf16  g_wo_h [HID*NH*VHD],  g_wo_l [HID*NH*VHD];
__device__ AL float g_qlat[NT*QL];
__device__ AL bf16  g_qln_h[NT*QL],       g_qln_l[NT*QL];
__device__ AL float g_q   [NT*HID];
__device__ AL float g_kv  [NT*KVA_N];
__device__ AL bf16  g_kvln_h[NT*KVL],     g_kvln_l[NT*KVL];
__device__ AL float g_kvb [NT*NH*KVOUT];
__device__ AL bf16  g_Qh_h[(u64)BB*NH*SS*QKD], g_Qh_l[(u64)BB*NH*SS*QKD];
__device__ AL bf16  g_Kh_h[(u64)BB*NH*SS*QKD], g_Kh_l[(u64)BB*NH*SS*QKD];
__device__ AL bf16  g_Vt_h[(u64)BB*NH*VHD*SS], g_Vt_l[(u64)BB*NH*VHD*SS];
__device__ AL float g_sc  [(u64)BB*NH*SS*SS];
__device__ AL bf16  g_P_h [(u64)BB*NH*SS*SS],  g_P_l [(u64)BB*NH*SS*SS];
__device__ AL bf16  g_at_h[NT*NH*VHD],    g_at_l[NT*NH*VHD];

// ------------------------------------------------------------------
// PTX helpers (all sm_80+ ISA: cp.async / ldmatrix / mma.sync bf16)
// ------------------------------------------------------------------
__device__ __forceinline__ uint32_t smem_u32(const void* p) {
    uint32_t a;
    asm("{ .reg .u64 t; cvta.to.shared.u64 t, %1; cvt.u32.u64 %0, t; }" : "=r"(a) : "l"(p));
    return a;
}
__device__ __forceinline__ void cp16(uint32_t dst, const void* src) {
    asm volatile("cp.async.cg.shared.global [%0], [%1], 16;" :: "r"(dst), "l"(src));
}
__device__ __forceinline__ void cp_commit() {
    asm volatile("cp.async.commit_group;" ::: "memory");
}
template<int N> __device__ __forceinline__ void cp_wait() {
    asm volatile("cp.async.wait_group %0;" :: "n"(N) : "memory");
}
__device__ __forceinline__ void ldm4(uint32_t* r, uint32_t addr) {
    asm volatile("ldmatrix.sync.aligned.m8n8.x4.shared.b16 {%0,%1,%2,%3}, [%4];"
        : "=r"(r[0]), "=r"(r[1]), "=r"(r[2]), "=r"(r[3]) : "r"(addr));
}
__device__ __forceinline__ void mma_bf16(float* c, const uint32_t* a, uint32_t b0, uint32_t b1) {
    asm volatile(
        "mma.sync.aligned.m16n8k16.row.col.f32.bf16.bf16.f32 "
        "{%0,%1,%2,%3}, {%4,%5,%6,%7}, {%8,%9}, {%0,%1,%2,%3};"
        : "+f"(c[0]), "+f"(c[1]), "+f"(c[2]), "+f"(c[3])
        : "r"(a[0]), "r"(a[1]), "r"(a[2]), "r"(a[3]), "r"(b0), "r"(b1));
}

// ------------------------------------------------------------------
// bf16x3-split warp-MMA GEMM: C[m][n] = sum_k A[m][k]*B[n][k]
// tile 128x128, BK=32, 256 threads (2x4 warps, 64x32 warp tile),
// 2-stage cp.async pipeline, padded smem stride 40 bf16 (80 B).
// mode 0: C = acc + bias (float out, ldc=Nw, store-guard n<Nw)
// mode 1: scores: acc*SCALE + mask  (z = bh)
// mode 2: PV: split to Oh/Ol with head scatter (z = bh)
// ------------------------------------------------------------------
#define LDSX 40
#define TSZ  (128*LDSX)          /* elems per tile (5120) */
#define STGE (4*TSZ)             /* elems per stage (20480) */
#define SMEM_BYTES (2*STGE*2)    /* 81920 bytes */

__global__ void __launch_bounds__(256, 1)
k_mma(const bf16* __restrict__ Ah, const bf16* __restrict__ Al,
      const bf16* __restrict__ Bh, const bf16* __restrict__ Bl,
      float* __restrict__ C, const float* __restrict__ bias,
      const float* __restrict__ mask,
      bf16* __restrict__ Oh, bf16* __restrict__ Ol,
      int M, int N, int K, int Nw, int mode)
{
    extern __shared__ bf16 sm[];
    const uint32_t sb = smem_u32(sm);

    const int tid  = threadIdx.x;
    const int wid  = tid >> 5, lane = tid & 31;
    const int wm   = (wid & 1) * 64;      // warp M offset in tile
    const int wn   = (wid >> 1) * 32;     // warp N offset in tile
    const int z    = blockIdx.z;
    const int m0   = blockIdx.y * 128, n0 = blockIdx.x * 128;

    if (mode == 1) {
        Ah += (u64)z*SS*QKD; Al += (u64)z*SS*QKD;
        Bh += (u64)z*SS*QKD; Bl += (u64)z*SS*QKD;
        C  += (u64)z*SS*SS;
    } else if (mode == 2) {
        Ah += (u64)z*SS*SS;  Al += (u64)z*SS*SS;
        Bh += (u64)z*VHD*SS; Bl += (u64)z*VHD*SS;
    }

    const u64 aoff0 = (u64)m0 * K;
    const u64 boff0 = (u64)n0 * K;
    const int NC = K >> 5;

    // ---- async fill of one stage: 4 tiles x 128 rows x 32 bf16 (4x16B/row)
    auto fill = [&](int stage, int c) {
        const uint32_t sbase = sb + stage * (STGE * 2);
        const u64 ka = aoff0 + c * 32;
        const u64 kb = boff0 + c * 32;
#pragma unroll
        for (int j = 0; j < 8; ++j) {
            const int i   = tid + j * 256;
            const int t   = i >> 9;
            const int row = (i >> 2) & 127;
            const int ch  = i & 3;
            const bf16* g = (t == 0) ? Ah : (t == 1) ? Al : (t == 2) ? Bh : Bl;
            const u64 base = (t < 2) ? ka : kb;
            const uint32_t dst = sbase + (t * TSZ + row * LDSX + ch * 8) * 2;
            cp16(dst, g + base + (u64)row * K + ch * 8);
        }
    };

    float acc[4][4][4];
#pragma unroll
    for (int a = 0; a < 4; ++a)
#pragma unroll
        for (int b = 0; b < 4; ++b)
#pragma unroll
            for (int d = 0; d < 4; ++d) acc[a][b][d] = 0.f;

    fill(0, 0);
    cp_commit();

    // precomputed ldmatrix lane addressing
    const int a_row = lane & 15;             // m row within 16
    const int a_kof = (lane >> 4) * 8;       // k offset 0/8
    const int b_row = (lane & 7) + ((lane >> 4) & 1) * 8;  // n row within 16
    const int b_kof = ((lane >> 3) & 1) * 8; // k offset 0/8

    for (int c = 0; c < NC; ++c) {
        if (c + 1 < NC) { fill((c + 1) & 1, c + 1); cp_commit(); cp_wait<1>(); }
        else            { cp_wait<0>(); }
        __syncthreads();

        const uint32_t st = sb + (c & 1) * (STGE * 2);
#pragma unroll
        for (int ks = 0; ks < 2; ++ks) {
            const int k0s = ks * 16;
            uint32_t aH[4][4], aLr[4][4], bH[2][4], bL[2][4];
#pragma unroll
            for (int mi = 0; mi < 4; ++mi) {
                const uint32_t ra = st + ((wm + mi * 16 + a_row) * LDSX + k0s + a_kof) * 2;
                ldm4(aH[mi],  ra);
                ldm4(aLr[mi], ra + TSZ * 2);
            }
#pragma unroll
            for (int np = 0; np < 2; ++np) {
                const uint32_t rb = st + (2 * TSZ + (wn + np * 16 + b_row) * LDSX + k0s + b_kof) * 2;
                ldm4(bH[np], rb);
                ldm4(bL[np], rb + TSZ * 2);
            }
#pragma unroll
            for (int mi = 0; mi < 4; ++mi) {
#pragma unroll
                for (int ni = 0; ni < 4; ++ni) {
                    const uint32_t b0h = bH[ni >> 1][(ni & 1) * 2];
                    const uint32_t b1h = bH[ni >> 1][(ni & 1) * 2 + 1];
                    const uint32_t b0l = bL[ni >> 1][(ni & 1) * 2];
                    const uint32_t b1l = bL[ni >> 1][(ni & 1) * 2 + 1];
                    mma_bf16(acc[mi][ni], aH[mi],  b0h, b1h);
                    mma_bf16(acc[mi][ni], aH[mi],  b0l, b1l);
                    mma_bf16(acc[mi][ni], aLr[mi], b0h, b1h);
                }
            }
        }
        __syncthreads();
    }

    // ---- epilogue
    const int er = lane >> 2;            // row within m16
    const int ec = (lane & 3) * 2;       // col within n8
#pragma unroll
    for (int mi = 0; mi < 4; ++mi) {
#pragma unroll
        for (int ni = 0; ni < 4; ++ni) {
            const int m = m0 + wm + mi * 16 + er;
            const int n = n0 + wn + ni * 8 + ec;
            const float* ac = acc[mi][ni];
            if (mode == 0) {
                if (n < Nw) {
                    const float b0 = bias[n], b1 = bias[n + 1];
                    float2 o0 = make_float2(ac[0] + b0, ac[1] + b1);
                    float2 o1 = make_float2(ac[2] + b0, ac[3] + b1);
                    *(float2*)&C[(u64)m * Nw + n]       = o0;
                    *(float2*)&C[(u64)(m + 8) * Nw + n] = o1;
                }
            } else if (mode == 1) {
                float2 mk0 = *(const float2*)&mask[(u64)m * SS + n];
                float2 mk1 = *(const float2*)&mask[(u64)(m + 8) * SS + n];
                float2 o0 = make_float2(ac[0] * SCALE + mk0.x, ac[1] * SCALE + mk0.y);
                float2 o1 = make_float2(ac[2] * SCALE + mk1.x, ac[3] * SCALE + mk1.y);
                *(float2*)&C[(u64)m * SS + n]       = o0;
                *(float2*)&C[(u64)(m + 8) * SS + n] = o1;
            } else {
                const int b = z >> 4, h = z & 15;
                const u64 r0o = (u64)(b * SS + m)     * (NH * VHD) + (u64)h * VHD + n;
                const u64 r1o = (u64)(b * SS + m + 8) * (NH * VHD) + (u64)h * VHD + n;
#pragma unroll
                for (int d = 0; d < 2; ++d) {
                    float v0 = ac[d], v1 = ac[2 + d];
                    bf16 h0 = __float2bfloat16(v0);
                    bf16 h1 = __float2bfloat16(v1);
                    Oh[r0o + d] = h0; Ol[r0o + d] = __float2bfloat16(v0 - __bfloat162float(h0));
                    Oh[r1o + d] = h1; Ol[r1o + d] = __float2bfloat16(v1 - __bfloat162float(h1));
                }
            }
        }
    }
}

// ------------------------------------------------------------------
// elementwise kernels
// ------------------------------------------------------------------
__global__ void k_split(const float* __restrict__ x, bf16* __restrict__ h,
                        bf16* __restrict__ l, int n)
{
    int i = blockIdx.x * 256 + threadIdx.x;
    if (i >= n) return;
    float v = x[i];
    bf16 hv = __float2bfloat16(v);
    h[i] = hv;
    l[i] = __float2bfloat16(v - __bfloat162float(hv));
}

__global__ void k_split_pad(const float* __restrict__ x, bf16* __restrict__ h,
                            bf16* __restrict__ l, int rows_src, int cols, int rows_dst)
{
    int i = blockIdx.x * 256 + threadIdx.x;
    if (i >= rows_dst * cols) return;
    int r = i / cols;
    float v = (r < rows_src) ? x[i] : 0.f;
    bf16 hv = __float2bfloat16(v);
    h[i] = hv;
    l[i] = __float2bfloat16(v - __bfloat162float(hv));
}

__global__ void __launch_bounds__(256)
k_rmsnorm(const float* __restrict__ X, const float* __restrict__ w,
          bf16* __restrict__ Yh, bf16* __restrict__ Yl,
          int W, int inStride, int outStride)
{
    int row = blockIdx.x;
    const float* x = X + (u64)row * inStride;
    float s = 0.f;
    for (int i = threadIdx.x; i < W; i += 256) { float v = x[i]; s += v * v; }
    __shared__ float red[256];
    red[threadIdx.x] = s; __syncthreads();
    for (int off = 128; off > 0; off >>= 1) {
        if (threadIdx.x < off) red[threadIdx.x] += red[threadIdx.x + off];
        __syncthreads();
    }
    float r = rsqrtf(red[0] / (float)W + 1e-6f);
    bf16* yh = Yh + (u64)row * outStride;
    bf16* yl = Yl + (u64)row * outStride;
    for (int i = threadIdx.x; i < W; i += 256) {
        float v = w[i] * (x[i] * r);
        bf16 hv = __float2bfloat16(v);
        yh[i] = hv;
        yl[i] = __float2bfloat16(v - __bfloat162float(hv));
    }
}

__device__ __forceinline__ float rope_val(float x1, float x2, int s, int i, int odd)
{
    float inv = powf(10000.f, -(float)(2 * i) / (float)ROPEd);
    float sn, cs;
    sincosf((float)s * inv, &sn, &cs);
    return odd ? (x1 * sn + x2 * cs) : (x1 * cs - x2 * sn);
}
__device__ __forceinline__ void wr_split(bf16* H, bf16* L, u64 o, float v)
{
    bf16 hv = __float2bfloat16(v);
    H[o] = hv;
    L[o] = __float2bfloat16(v - __bfloat162float(hv));
}

__global__ void k_prep_q()
{
    int idx = blockIdx.x * blockDim.x + threadIdx.x;
    if (idx >= BB * SS * NH * QKD) return;
    int d = idx % QKD;
    int h = (idx / QKD) % NH;
    int s = (idx / (QKD * NH)) % SS;
    int b =  idx / (QKD * NH * SS);
    const float* qrow = g_q + (u64)(b * SS + s) * HID + h * QKD;
    float val;
    if (d < NOPEd) val = qrow[d];
    else {
        int i = (d - NOPEd) >> 1;
        val = rope_val(qrow[NOPEd + 2 * i], qrow[NOPEd + 2 * i + 1], s, i, (d - NOPEd) & 1);
    }
    wr_split(g_Qh_h, g_Qh_l, ((u64)(b * NH + h) * SS + s) * QKD + d, val);
}

__global__ void k_prep_k()
{
    int idx = blockIdx.x * blockDim.x + threadIdx.x;
    if (idx >= BB * SS * NH * QKD) return;
    int d = idx % QKD;
    int h = (idx / QKD) % NH;
    int s = (idx / (QKD * NH)) % SS;
    int b =  idx / (QKD * NH * SS);
    float val;
    if (d < NOPEd) {
        val = g_kvb[(u64)(b * SS + s) * (NH * KVOUT) + h * KVOUT + d];
    } else {
        int i = (d - NOPEd) >> 1;
        const float* kr = g_kv + (u64)(b * SS + s) * KVA_N + KVL;
        val = rope_val(kr[2 * i], kr[2 * i + 1], s, i, (d - NOPEd) & 1);
    }
    wr_split(g_Kh_h, g_Kh_l, ((u64)(b * NH + h) * SS + s) * QKD + d, val);
}

__global__ void k_prep_v()   // V transposed: [b][h][d][t]
{
    int idx = blockIdx.x * blockDim.x + threadIdx.x;
    if (idx >= BB * NH * VHD * SS) return;
    int s = idx % SS;
    int d = (idx / SS) % VHD;
    int h = (idx / (SS * VHD)) % NH;
    int b =  idx / (SS * VHD * NH);
    float v = g_kvb[(u64)(b * SS + s) * (NH * KVOUT) + h * KVOUT + NOPEd + d];
    wr_split(g_Vt_h, g_Vt_l, (u64)idx, v);
}

__global__ void __launch_bounds__(256)
k_softmax()
{
    const float* p = g_sc + (u64)blockIdx.x * SS;
    int t = threadIdx.x;
    float4 v = *(const float4*)&p[t * 4];
    __shared__ float red[256];
    float mx = fmaxf(fmaxf(v.x, v.y), fmaxf(v.z, v.w));
    red[t] = mx; __syncthreads();
    for (int off = 128; off > 0; off >>= 1) {
        if (t < off) red[t] = fmaxf(red[t], red[t + off]);
        __syncthreads();
    }
    mx = red[0]; __syncthreads();
    v.x = expf(v.x - mx); v.y = expf(v.y - mx);
    v.z = expf(v.z - mx); v.w = expf(v.w - mx);
    red[t] = v.x + v.y + v.z + v.w; __syncthreads();
    for (int off = 128; off > 0; off >>= 1) {
        if (t < off) red[t] += red[t + off];
        __syncthreads();
    }
    float inv = 1.0f / red[0];
    u64 o = (u64)blockIdx.x * SS + t * 4;
    wr_split(g_P_h, g_P_l, o + 0, v.x * inv);
    wr_split(g_P_h, g_P_l, o + 1, v.y * inv);
    wr_split(g_P_h, g_P_l, o + 2, v.z * inv);
    wr_split(g_P_h, g_P_l, o + 3, v.w * inv);
}

// ------------------------------------------------------------------
// launch
// ------------------------------------------------------------------
static inline void* sym(const void* s) { void* p; cudaGetSymbolAddress(&p, s); return p; }

extern "C" void kernel_launch(void* const* d_in, const int* in_sizes, int n_in,
                              void* d_out, int out_size)
{
    const float* hs        = (const float*)d_in[0];
    const float* mask      = (const float*)d_in[1];
    const float* wq_a_w    = (const float*)d_in[2];
    const float* wq_a_b    = (const float*)d_in[3];
    const float* q_norm_w  = (const float*)d_in[4];
    const float* wq_b_w    = (const float*)d_in[5];
    const float* wq_b_b    = (const float*)d_in[6];
    const float* wkv_a_w   = (const float*)d_in[7];
    const float* wkv_a_b   = (const float*)d_in[8];
    const float* kv_norm_w = (const float*)d_in[9];
    const float* wkv_b_w   = (const float*)d_in[10];
    const float* wkv_b_b   = (const float*)d_in[11];
    const float* wo_w      = (const float*)d_in[12];
    const float* wo_b      = (const float*)d_in[13];
    float* out = (float*)d_out;

    static int smem_set = 0;
    if (!smem_set) {
        cudaFuncSetAttribute(k_mma, cudaFuncAttributeMaxDynamicSharedMemorySize, SMEM_BYTES);
        smem_set = 1;
    }

    bf16 *hs_h=(bf16*)sym(g_hs_h), *hs_l=(bf16*)sym(g_hs_l);
    bf16 *wqa_h=(bf16*)sym(g_wqa_h), *wqa_l=(bf16*)sym(g_wqa_l);
    bf16 *wqb_h=(bf16*)sym(g_wqb_h), *wqb_l=(bf16*)sym(g_wqb_l);
    bf16 *wkva_h=(bf16*)sym(g_wkva_h), *wkva_l=(bf16*)sym(g_wkva_l);
    bf16 *wkvb_h=(bf16*)sym(g_wkvb_h), *wkvb_l=(bf16*)sym(g_wkvb_l);
    bf16 *wo_h=(bf16*)sym(g_wo_h), *wo_l=(bf16*)sym(g_wo_l);
    float *qlat=(float*)sym(g_qlat), *q=(float*)sym(g_q);
    bf16 *qln_h=(bf16*)sym(g_qln_h), *qln_l=(bf16*)sym(g_qln_l);
    float *kv=(float*)sym(g_kv), *kvb=(float*)sym(g_kvb);
    bf16 *kvln_h=(bf16*)sym(g_kvln_h), *kvln_l=(bf16*)sym(g_kvln_l);
    bf16 *Qh_h=(bf16*)sym(g_Qh_h), *Qh_l=(bf16*)sym(g_Qh_l);
    bf16 *Kh_h=(bf16*)sym(g_Kh_h), *Kh_l=(bf16*)sym(g_Kh_l);
    bf16 *Vt_h=(bf16*)sym(g_Vt_h), *Vt_l=(bf16*)sym(g_Vt_l);
    float *sc=(float*)sym(g_sc);
    bf16 *P_h=(bf16*)sym(g_P_h), *P_l=(bf16*)sym(g_P_l);
    bf16 *at_h=(bf16*)sym(g_at_h), *at_l=(bf16*)sym(g_at_l);

    // ---- splits of inputs/weights
    k_split<<<(NT*HID + 255)/256, 256>>>(hs, hs_h, hs_l, NT*HID);
    k_split<<<(QL*HID + 255)/256, 256>>>(wq_a_w, wqa_h, wqa_l, QL*HID);
    k_split<<<(HID*QL + 255)/256, 256>>>(wq_b_w, wqb_h, wqb_l, HID*QL);
    k_split_pad<<<(KVA_NP*HID + 255)/256, 256>>>(wkv_a_w, wkva_h, wkva_l, KVA_N, HID, KVA_NP);
    k_split<<<(NH*KVOUT*KVL + 255)/256, 256>>>(wkv_b_w, wkvb_h, wkvb_l, NH*KVOUT*KVL);
    k_split<<<(HID*NH*VHD + 255)/256, 256>>>(wo_w, wo_h, wo_l, HID*NH*VHD);

    // ---- q path
    k_mma<<<dim3(QL/128, NT/128, 1), 256, SMEM_BYTES>>>(
        hs_h, hs_l, wqa_h, wqa_l, qlat, wq_a_b, nullptr, nullptr, nullptr,
        NT, QL, HID, QL, 0);
    k_rmsnorm<<<NT, 256>>>(qlat, q_norm_w, qln_h, qln_l, QL, QL, QL);
    k_mma<<<dim3(HID/128, NT/128, 1), 256, SMEM_BYTES>>>(
        qln_h, qln_l, wqb_h, wqb_l, q, wq_b_b, nullptr, nullptr, nullptr,
        NT, HID, QL, HID, 0);

    // ---- kv path
    k_mma<<<dim3(KVA_NP/128, NT/128, 1), 256, SMEM_BYTES>>>(
        hs_h, hs_l, wkva_h, wkva_l, kv, wkv_a_b, nullptr, nullptr, nullptr,
        NT, KVA_NP, HID, KVA_N, 0);
    k_rmsnorm<<<NT, 256>>>(kv, kv_norm_w, kvln_h, kvln_l, KVL, KVA_N, KVL);
    k_mma<<<dim3(NH*KVOUT/128, NT/128, 1), 256, SMEM_BYTES>>>(
        kvln_h, kvln_l, wkvb_h, wkvb_l, kvb, wkv_b_b, nullptr, nullptr, nullptr,
        NT, NH*KVOUT, KVL, NH*KVOUT, 0);

    // ---- head gather + rope + transpose (with split)
    k_prep_q<<<(BB*SS*NH*QKD + 255)/256, 256>>>();
    k_prep_k<<<(BB*SS*NH*QKD + 255)/256, 256>>>();
    k_prep_v<<<(BB*NH*VHD*SS + 255)/256, 256>>>();

    // ---- attention
    k_mma<<<dim3(SS/128, SS/128, BB*NH), 256, SMEM_BYTES>>>(
        Qh_h, Qh_l, Kh_h, Kh_l, sc, nullptr, mask, nullptr, nullptr,
        SS, SS, QKD, SS, 1);
    k_softmax<<<BB*NH*SS, 256>>>();
    k_mma<<<dim3(VHD/128, SS/128, BB*NH), 256, SMEM_BYTES>>>(
        P_h, P_l, Vt_h, Vt_l, nullptr, nullptr, nullptr, at_h, at_l,
        SS, VHD, SS, VHD, 2);

    // ---- output projection
    k_mma<<<dim3(HID/128, NT/128, 1), 256, SMEM_BYTES>>>(
        at_h, at_l, wo_h, wo_l, out, wo_b, nullptr, nullptr, nullptr,
        NT, HID, NH*VHD, HID, 0);
}

// round 6
// speedup vs baseline: 1.3184x; 1.3184x over previous
#include <cuda_runtime.h>
#include <cuda_fp16.h>
#include <math.h>
#include <stdint.h>

typedef unsigned long long u64;
typedef __half h16;

#define BB 2
#define SS 1024
#define HID 3072
#define NH 16
#define QL 1536
#define KVL 512
#define NOPEd 128
#define ROPEd 64
#define QKD 192
#define VHD 128
#define NT (BB*SS)
#define KVOUT 256
#define KVA_N 576          /* KVL + ROPE */
#define KVA_NP 640         /* padded to multiple of 128 */
#define SCALE 0.07216878364870323f

// ------------------------------------------------------------------
// scratch (device globals)
// ------------------------------------------------------------------
#define AL __align__(256)
__device__ AL h16   g_hs_h [NT*HID],      g_hs_l [NT*HID];
__device__ AL h16   g_wqa [QL*HID];
__device__ AL h16   g_wqb [HID*QL];
__device__ AL h16   g_wkva[KVA_NP*HID];
__device__ AL h16   g_wkvb[NH*KVOUT*KVL];
__device__ AL h16   g_wo  [HID*NH*VHD];
__device__ AL float g_qlat[NT*QL];
__device__ AL h16   g_qln_h[NT*QL],       g_qln_l[NT*QL];
__device__ AL float g_q   [NT*HID];
__device__ AL float g_kv  [NT*KVA_N];
__device__ AL h16   g_kvln_h[NT*KVL],     g_kvln_l[NT*KVL];
__device__ AL float g_kvb [NT*NH*KVOUT];
__device__ AL h16   g_Qh_h[(u64)BB*NH*SS*QKD], g_Qh_l[(u64)BB*NH*SS*QKD];
__device__ AL h16   g_Kh  [(u64)BB*NH*SS*QKD];
__device__ AL h16   g_Vt  [(u64)BB*NH*VHD*SS];   /* [b][h][d][t] */
__device__ AL float g_sc  [(u64)BB*NH*SS*SS];
__device__ AL h16   g_P_h [(u64)BB*NH*SS*SS],  g_P_l [(u64)BB*NH*SS*SS];
__device__ AL h16   g_at_h[NT*NH*VHD],    g_at_l[NT*NH*VHD];

// ------------------------------------------------------------------
// PTX helpers (sm_80+ ISA: cp.async / ldmatrix / mma.sync fp16)
// ------------------------------------------------------------------
__device__ __forceinline__ uint32_t smem_u32(const void* p) {
    uint32_t a;
    asm("{ .reg .u64 t; cvta.to.shared.u64 t, %1; cvt.u32.u64 %0, t; }" : "=r"(a) : "l"(p));
    return a;
}
__device__ __forceinline__ void cp16(uint32_t dst, const void* src) {
    asm volatile("cp.async.cg.shared.global [%0], [%1], 16;" :: "r"(dst), "l"(src));
}
__device__ __forceinline__ void cp_commit() {
    asm volatile("cp.async.commit_group;" ::: "memory");
}
template<int N> __device__ __forceinline__ void cp_wait() {
    asm volatile("cp.async.wait_group %0;" :: "n"(N) : "memory");
}
__device__ __forceinline__ void ldm4(uint32_t* r, uint32_t addr) {
    asm volatile("ldmatrix.sync.aligned.m8n8.x4.shared.b16 {%0,%1,%2,%3}, [%4];"
        : "=r"(r[0]), "=r"(r[1]), "=r"(r[2]), "=r"(r[3]) : "r"(addr));
}
__device__ __forceinline__ void mma_f16(float* c, const uint32_t* a, uint32_t b0, uint32_t b1) {
    asm volatile(
        "mma.sync.aligned.m16n8k16.row.col.f32.f16.f16.f32 "
        "{%0,%1,%2,%3}, {%4,%5,%6,%7}, {%8,%9}, {%0,%1,%2,%3};"
        : "+f"(c[0]), "+f"(c[1]), "+f"(c[2]), "+f"(c[3])
        : "r"(a[0]), "r"(a[1]), "r"(a[2]), "r"(a[3]), "r"(b0), "r"(b1));
}

// ------------------------------------------------------------------
// fp16 2-term split GEMM: C[m][n] = sum_k (Ah+Al)[m][k]*B[n][k]
// tile 128x128, BK=32, 256 threads (2x4 warps, 64x32 warp tile),
// 4-stage cp.async pipeline, padded smem stride 40 h16 (80 B).
// mode 0: C = acc + bias (float out, ldc=Nw, store-guard n<Nw)
// mode 1: scores: acc*SCALE + mask  (z = bh)
// mode 2: PV: split to Oh/Ol with head scatter (z = bh)
// ------------------------------------------------------------------
#define LDSX 40
#define TSZ  (128*LDSX)          /* elems per tile (5120) */
#define STGB (3*TSZ*2)           /* bytes per stage (30720): Ah, Al, B */
#define NSTG 4
#define SMEM_BYTES (NSTG*STGB)   /* 122880 bytes */

__global__ void __launch_bounds__(256, 1)
k_mma(const h16* __restrict__ Ah, const h16* __restrict__ Al,
      const h16* __restrict__ B,
      float* __restrict__ C, const float* __restrict__ bias,
      const float* __restrict__ mask,
      h16* __restrict__ Oh, h16* __restrict__ Ol,
      int M, int N, int K, int Nw, int mode)
{
    extern __shared__ h16 sm[];
    const uint32_t sb = smem_u32(sm);

    const int tid  = threadIdx.x;
    const int wid  = tid >> 5, lane = tid & 31;
    const int wm   = (wid & 1) * 64;      // warp M offset in tile
    const int wn   = (wid >> 1) * 32;     // warp N offset in tile
    const int z    = blockIdx.z;
    const int m0   = blockIdx.y * 128, n0 = blockIdx.x * 128;

    if (mode == 1) {
        Ah += (u64)z*SS*QKD; Al += (u64)z*SS*QKD;
        B  += (u64)z*SS*QKD;
        C  += (u64)z*SS*SS;
    } else if (mode == 2) {
        Ah += (u64)z*SS*SS;  Al += (u64)z*SS*SS;
        B  += (u64)z*VHD*SS;
    }

    const u64 aoff0 = (u64)m0 * K;
    const u64 boff0 = (u64)n0 * K;
    const int NC = K >> 5;

    // async fill of one stage: 3 tiles x 128 rows x 32 h16 (4x16B/row)
    auto fill = [&](int stage, int c) {
        const uint32_t sbase = sb + stage * STGB;
        const u64 ka = aoff0 + c * 32;
        const u64 kb = boff0 + c * 32;
#pragma unroll
        for (int j = 0; j < 6; ++j) {
            const int i   = tid + j * 256;
            const int t   = i >> 9;                  // 0:Ah 1:Al 2:B
            const int row = (i >> 2) & 127;
            const int ch  = i & 3;
            const h16* g  = (t == 0) ? Ah : (t == 1) ? Al : B;
            const u64 base = (t < 2) ? ka : kb;
            const uint32_t dst = sbase + (t * TSZ + row * LDSX + ch * 8) * 2;
            cp16(dst, g + base + (u64)row * K + ch * 8);
        }
    };

    float acc[4][4][4];
#pragma unroll
    for (int a = 0; a < 4; ++a)
#pragma unroll
        for (int b = 0; b < 4; ++b)
#pragma unroll
            for (int d = 0; d < 4; ++d) acc[a][b][d] = 0.f;

    // prologue: fill first 3 stages
#pragma unroll
    for (int p = 0; p < NSTG - 1; ++p) {
        if (p < NC) fill(p, p);
        cp_commit();
    }

    // ldmatrix lane addressing
    const int a_row = lane & 15;
    const int a_kof = (lane >> 4) * 8;
    const int b_row = (lane & 7) + ((lane >> 4) & 1) * 8;
    const int b_kof = ((lane >> 3) & 1) * 8;

    for (int c = 0; c < NC; ++c) {
        cp_wait<NSTG - 2>();
        __syncthreads();
        if (c + NSTG - 1 < NC) fill((c + NSTG - 1) & (NSTG - 1), c + NSTG - 1);
        cp_commit();

        const uint32_t st = sb + (c & (NSTG - 1)) * STGB;
#pragma unroll
        for (int ks = 0; ks < 2; ++ks) {
            const int k0s = ks * 16;
            uint32_t aH[4][4], aL[4][4], bS[2][4];
#pragma unroll
            for (int mi = 0; mi < 4; ++mi) {
                const uint32_t ra = st + ((wm + mi * 16 + a_row) * LDSX + k0s + a_kof) * 2;
                ldm4(aH[mi], ra);
                ldm4(aL[mi], ra + TSZ * 2);
            }
#pragma unroll
            for (int np = 0; np < 2; ++np) {
                const uint32_t rb = st + (2 * TSZ + (wn + np * 16 + b_row) * LDSX + k0s + b_kof) * 2;
                ldm4(bS[np], rb);
            }
#pragma unroll
            for (int mi = 0; mi < 4; ++mi) {
#pragma unroll
                for (int ni = 0; ni < 4; ++ni) {
                    const uint32_t b0 = bS[ni >> 1][(ni & 1) * 2];
                    const uint32_t b1 = bS[ni >> 1][(ni & 1) * 2 + 1];
                    mma_f16(acc[mi][ni], aH[mi], b0, b1);
                    mma_f16(acc[mi][ni], aL[mi], b0, b1);
                }
            }
        }
    }

    // ---- epilogue
    const int er = lane >> 2;
    const int ec = (lane & 3) * 2;
#pragma unroll
    for (int mi = 0; mi < 4; ++mi) {
#pragma unroll
        for (int ni = 0; ni < 4; ++ni) {
            const int m = m0 + wm + mi * 16 + er;
            const int n = n0 + wn + ni * 8 + ec;
            const float* ac = acc[mi][ni];
            if (mode == 0) {
                if (n < Nw) {
                    const float b0 = bias[n], b1 = bias[n + 1];
                    float2 o0 = make_float2(ac[0] + b0, ac[1] + b1);
                    float2 o1 = make_float2(ac[2] + b0, ac[3] + b1);
                    *(float2*)&C[(u64)m * Nw + n]       = o0;
                    *(float2*)&C[(u64)(m + 8) * Nw + n] = o1;
                }
            } else if (mode == 1) {
                float2 mk0 = *(const float2*)&mask[(u64)m * SS + n];
                float2 mk1 = *(const float2*)&mask[(u64)(m + 8) * SS + n];
                float2 o0 = make_float2(ac[0] * SCALE + mk0.x, ac[1] * SCALE + mk0.y);
                float2 o1 = make_float2(ac[2] * SCALE + mk1.x, ac[3] * SCALE + mk1.y);
                *(float2*)&C[(u64)m * SS + n]       = o0;
                *(float2*)&C[(u64)(m + 8) * SS + n] = o1;
            } else {
                const int b = z >> 4, h = z & 15;
                const u64 r0o = (u64)(b * SS + m)     * (NH * VHD) + (u64)h * VHD + n;
                const u64 r1o = (u64)(b * SS + m + 8) * (NH * VHD) + (u64)h * VHD + n;
#pragma unroll
                for (int d = 0; d < 2; ++d) {
                    float v0 = ac[d], v1 = ac[2 + d];
                    h16 h0 = __float2half_rn(v0);
                    h16 h1 = __float2half_rn(v1);
                    Oh[r0o + d] = h0; Ol[r0o + d] = __float2half_rn(v0 - __half2float(h0));
                    Oh[r1o + d] = h1; Ol[r1o + d] = __float2half_rn(v1 - __half2float(h1));
                }
            }
        }
    }
}

// ------------------------------------------------------------------
// elementwise kernels
// ------------------------------------------------------------------
__global__ void k_split(const float* __restrict__ x, h16* __restrict__ h,
                        h16* __restrict__ l, int n)
{
    int i = blockIdx.x * 256 + threadIdx.x;
    if (i >= n) return;
    float v = x[i];
    h16 hv = __float2half_rn(v);
    h[i] = hv;
    l[i] = __float2half_rn(v - __half2float(hv));
}

__global__ void k_split1(const float* __restrict__ x, h16* __restrict__ o, int n)
{
    int i = blockIdx.x * 256 + threadIdx.x;
    if (i >= n) return;
    o[i] = __float2half_rn(x[i]);
}

__global__ void k_split1_pad(const float* __restrict__ x, h16* __restrict__ o,
                             int rows_src, int cols, int rows_dst)
{
    int i = blockIdx.x * 256 + threadIdx.x;
    if (i >= rows_dst * cols) return;
    int r = i / cols;
    o[i] = __float2half_rn((r < rows_src) ? x[i] : 0.f);
}

__global__ void __launch_bounds__(256)
k_rmsnorm(const float* __restrict__ X, const float* __restrict__ w,
          h16* __restrict__ Yh, h16* __restrict__ Yl,
          int W, int inStride, int outStride)
{
    int row = blockIdx.x;
    const float* x = X + (u64)row * inStride;
    float s = 0.f;
    for (int i = threadIdx.x; i < W; i += 256) { float v = x[i]; s += v * v; }
    __shared__ float red[256];
    red[threadIdx.x] = s; __syncthreads();
    for (int off = 128; off > 0; off >>= 1) {
        if (threadIdx.x < off) red[threadIdx.x] += red[threadIdx.x + off];
        __syncthreads();
    }
    float r = rsqrtf(red[0] / (float)W + 1e-6f);
    h16* yh = Yh + (u64)row * outStride;
    h16* yl = Yl + (u64)row * outStride;
    for (int i = threadIdx.x; i < W; i += 256) {
        float v = w[i] * (x[i] * r);
        h16 hv = __float2half_rn(v);
        yh[i] = hv;
        yl[i] = __float2half_rn(v - __half2float(hv));
    }
}

__device__ __forceinline__ float rope_val(float x1, float x2, int s, int i, int odd)
{
    float inv = powf(10000.f, -(float)(2 * i) / (float)ROPEd);
    float sn, cs;
    sincosf((float)s * inv, &sn, &cs);
    return odd ? (x1 * sn + x2 * cs) : (x1 * cs - x2 * sn);
}
__device__ __forceinline__ void wr_split(h16* H, h16* L, u64 o, float v)
{
    h16 hv = __float2half_rn(v);
    H[o] = hv;
    L[o] = __float2half_rn(v - __half2float(hv));
}

__global__ void k_prep_q()
{
    int idx = blockIdx.x * blockDim.x + threadIdx.x;
    if (idx >= BB * SS * NH * QKD) return;
    int d = idx % QKD;
    int h = (idx / QKD) % NH;
    int s = (idx / (QKD * NH)) % SS;
    int b =  idx / (QKD * NH * SS);
    const float* qrow = g_q + (u64)(b * SS + s) * HID + h * QKD;
    float val;
    if (d < NOPEd) val = qrow[d];
    else {
        int i = (d - NOPEd) >> 1;
        val = rope_val(qrow[NOPEd + 2 * i], qrow[NOPEd + 2 * i + 1], s, i, (d - NOPEd) & 1);
    }
    wr_split(g_Qh_h, g_Qh_l, ((u64)(b * NH + h) * SS + s) * QKD + d, val);
}

__global__ void k_prep_k()
{
    int idx = blockIdx.x * blockDim.x + threadIdx.x;
    if (idx >= BB * SS * NH * QKD) return;
    int d = idx % QKD;
    int h = (idx / QKD) % NH;
    int s = (idx / (QKD * NH)) % SS;
    int b =  idx / (QKD * NH * SS);
    float val;
    if (d < NOPEd) {
        val = g_kvb[(u64)(b * SS + s) * (NH * KVOUT) + h * KVOUT + d];
    } else {
        int i = (d - NOPEd) >> 1;
        const float* kr = g_kv + (u64)(b * SS + s) * KVA_N + KVL;
        val = rope_val(kr[2 * i], kr[2 * i + 1], s, i, (d - NOPEd) & 1);
    }
    g_Kh[((u64)(b * NH + h) * SS + s) * QKD + d] = __float2half_rn(val);
}

__global__ void k_prep_v()   // V transposed: [b][h][d][t], single fp16
{
    int idx = blockIdx.x * blockDim.x + threadIdx.x;
    if (idx >= BB * NH * VHD * SS) return;
    int s = idx % SS;
    int d = (idx / SS) % VHD;
    int h = (idx / (SS * VHD)) % NH;
    int b =  idx / (SS * VHD * NH);
    float v = g_kvb[(u64)(b * SS + s) * (NH * KVOUT) + h * KVOUT + NOPEd + d];
    g_Vt[idx] = __float2half_rn(v);
}

__global__ void __launch_bounds__(256)
k_softmax()
{
    const float* p = g_sc + (u64)blockIdx.x * SS;
    int t = threadIdx.x;
    float4 v = *(const float4*)&p[t * 4];
    __shared__ float red[256];
    float mx = fmaxf(fmaxf(v.x, v.y), fmaxf(v.z, v.w));
    red[t] = mx; __syncthreads();
    for (int off = 128; off > 0; off >>= 1) {
        if (t < off) red[t] = fmaxf(red[t], red[t + off]);
        __syncthreads();
    }
    mx = red[0]; __syncthreads();
    v.x = expf(v.x - mx); v.y = expf(v.y - mx);
    v.z = expf(v.z - mx); v.w = expf(v.w - mx);
    red[t] = v.x + v.y + v.z + v.w; __syncthreads();
    for (int off = 128; off > 0; off >>= 1) {
        if (t < off) red[t] += red[t + off];
        __syncthreads();
    }
    float inv = 1.0f / red[0];
    u64 o = (u64)blockIdx.x * SS + t * 4;
    wr_split(g_P_h, g_P_l, o + 0, v.x * inv);
    wr_split(g_P_h, g_P_l, o + 1, v.y * inv);
    wr_split(g_P_h, g_P_l, o + 2, v.z * inv);
    wr_split(g_P_h, g_P_l, o + 3, v.w * inv);
}

// ------------------------------------------------------------------
// launch
// ------------------------------------------------------------------
static inline void* sym(const void* s) { void* p; cudaGetSymbolAddress(&p, s); return p; }

extern "C" void kernel_launch(void* const* d_in, const int* in_sizes, int n_in,
                              void* d_out, int out_size)
{
    const float* hs        = (const float*)d_in[0];
    const float* mask      = (const float*)d_in[1];
    const float* wq_a_w    = (const float*)d_in[2];
    const float* wq_a_b    = (const float*)d_in[3];
    const float* q_norm_w  = (const float*)d_in[4];
    const float* wq_b_w    = (const float*)d_in[5];
    const float* wq_b_b    = (const float*)d_in[6];
    const float* wkv_a_w   = (const float*)d_in[7];
    const float* wkv_a_b   = (const float*)d_in[8];
    const float* kv_norm_w = (const float*)d_in[9];
    const float* wkv_b_w   = (const float*)d_in[10];
    const float* wkv_b_b   = (const float*)d_in[11];
    const float* wo_w      = (const float*)d_in[12];
    const float* wo_b      = (const float*)d_in[13];
    float* out = (float*)d_out;

    static int smem_set = 0;
    if (!smem_set) {
        cudaFuncSetAttribute(k_mma, cudaFuncAttributeMaxDynamicSharedMemorySize, SMEM_BYTES);
        smem_set = 1;
    }

    h16 *hs_h=(h16*)sym(g_hs_h), *hs_l=(h16*)sym(g_hs_l);
    h16 *wqa=(h16*)sym(g_wqa), *wqb=(h16*)sym(g_wqb);
    h16 *wkva=(h16*)sym(g_wkva), *wkvb=(h16*)sym(g_wkvb), *wo=(h16*)sym(g_wo);
    float *qlat=(float*)sym(g_qlat), *q=(float*)sym(g_q);
    h16 *qln_h=(h16*)sym(g_qln_h), *qln_l=(h16*)sym(g_qln_l);
    float *kv=(float*)sym(g_kv), *kvb=(float*)sym(g_kvb);
    h16 *kvln_h=(h16*)sym(g_kvln_h), *kvln_l=(h16*)sym(g_kvln_l);
    h16 *Qh_h=(h16*)sym(g_Qh_h), *Qh_l=(h16*)sym(g_Qh_l);
    h16 *Kh=(h16*)sym(g_Kh), *Vt=(h16*)sym(g_Vt);
    float *sc=(float*)sym(g_sc);
    h16 *P_h=(h16*)sym(g_P_h), *P_l=(h16*)sym(g_P_l);
    h16 *at_h=(h16*)sym(g_at_h), *at_l=(h16*)sym(g_at_l);

    // ---- splits of inputs/weights
    k_split <<<(NT*HID + 255)/256, 256>>>(hs, hs_h, hs_l, NT*HID);
    k_split1<<<(QL*HID + 255)/256, 256>>>(wq_a_w, wqa, QL*HID);
    k_split1<<<(HID*QL + 255)/256, 256>>>(wq_b_w, wqb, HID*QL);
    k_split1_pad<<<(KVA_NP*HID + 255)/256, 256>>>(wkv_a_w, wkva, KVA_N, HID, KVA_NP);
    k_split1<<<(NH*KVOUT*KVL + 255)/256, 256>>>(wkv_b_w, wkvb, NH*KVOUT*KVL);
    k_split1<<<(HID*NH*VHD + 255)/256, 256>>>(wo_w, wo, HID*NH*VHD);

    // ---- q path
    k_mma<<<dim3(QL/128, NT/128, 1), 256, SMEM_BYTES>>>(
        hs_h, hs_l, wqa, qlat, wq_a_b, nullptr, nullptr, nullptr,
        NT, QL, HID, QL, 0);
    k_rmsnorm<<<NT, 256>>>(qlat, q_norm_w, qln_h, qln_l, QL, QL, QL);
    k_mma<<<dim3(HID/128, NT/128, 1), 256, SMEM_BYTES>>>(
        qln_h, qln_l, wqb, q, wq_b_b, nullptr, nullptr, nullptr,
        NT, HID, QL, HID, 0);

    // ---- kv path
    k_mma<<<dim3(KVA_NP/128, NT/128, 1), 256, SMEM_BYTES>>>(
        hs_h, hs_l, wkva, kv, wkv_a_b, nullptr, nullptr, nullptr,
        NT, KVA_NP, HID, KVA_N, 0);
    k_rmsnorm<<<NT, 256>>>(kv, kv_norm_w, kvln_h, kvln_l, KVL, KVA_N, KVL);
    k_mma<<<dim3(NH*KVOUT/128, NT/128, 1), 256, SMEM_BYTES>>>(
        kvln_h, kvln_l, wkvb, kvb, wkv_b_b, nullptr, nullptr, nullptr,
        NT, NH*KVOUT, KVL, NH*KVOUT, 0);

    // ---- head gather + rope + transpose
    k_prep_q<<<(BB*SS*NH*QKD + 255)/256, 256>>>();
    k_prep_k<<<(BB*SS*NH*QKD + 255)/256, 256>>>();
    k_prep_v<<<(BB*NH*VHD*SS + 255)/256, 256>>>();

    // ---- attention
    k_mma<<<dim3(SS/128, SS/128, BB*NH), 256, SMEM_BYTES>>>(
        Qh_h, Qh_l, Kh, sc, nullptr, mask, nullptr, nullptr,
        SS, SS, QKD, SS, 1);
    k_softmax<<<BB*NH*SS, 256>>>();
    k_mma<<<dim3(VHD/128, SS/128, BB*NH), 256, SMEM_BYTES>>>(
        P_h, P_l, Vt, nullptr, nullptr, nullptr, at_h, at_l,
        SS, VHD, SS, VHD, 2);

    // ---- output projection
    k_mma<<<dim3(HID/128, NT/128, 1), 256, SMEM_BYTES>>>(
        at_h, at_l, wo, out, wo_b, nullptr, nullptr, nullptr,
        NT, HID, NH*VHD, HID, 0);
}

// round 7
// speedup vs baseline: 1.3196x; 1.0010x over previous
#include <cuda_runtime.h>
#include <cuda_fp16.h>
#include <math.h>
#include <stdint.h>

typedef unsigned long long u64;
typedef __half h16;

#define BB 2
#define SS 1024
#define HID 3072
#define NH 16
#define QL 1536
#define KVL 512
#define NOPEd 128
#define ROPEd 64
#define QKD 192
#define VHD 128
#define NT (BB*SS)
#define KVOUT 256
#define KVA_N 576          /* KVL + ROPE */
#define KVA_NP 640         /* padded to multiple of 128 */
#define SCALE 0.07216878364870323f

// ------------------------------------------------------------------
// scratch (device globals)
// ------------------------------------------------------------------
#define AL __align__(256)
__device__ AL h16   g_hs_h [NT*HID],      g_hs_l [NT*HID];
__device__ AL h16   g_wqa [QL*HID];
__device__ AL h16   g_wqb [HID*QL];
__device__ AL h16   g_wkva[KVA_NP*HID];
__device__ AL h16   g_wkvb[NH*KVOUT*KVL];
__device__ AL h16   g_wo  [HID*NH*VHD];
__device__ AL float g_qlat[NT*QL];
__device__ AL h16   g_qln_h[NT*QL],       g_qln_l[NT*QL];
__device__ AL float g_q   [NT*HID];
__device__ AL float g_kv  [NT*KVA_N];
__device__ AL h16   g_kvln_h[NT*KVL],     g_kvln_l[NT*KVL];
__device__ AL float g_kvb [NT*NH*KVOUT];
__device__ AL h16   g_Qh_h[(u64)BB*NH*SS*QKD], g_Qh_l[(u64)BB*NH*SS*QKD];
__device__ AL h16   g_Kh  [(u64)BB*NH*SS*QKD];
__device__ AL h16   g_Vt  [(u64)BB*NH*VHD*SS];   /* [b][h][d][t] */
__device__ AL float g_sc  [(u64)BB*NH*SS*SS];
__device__ AL h16   g_P_h [(u64)BB*NH*SS*SS],  g_P_l [(u64)BB*NH*SS*SS];
__device__ AL h16   g_at_h[NT*NH*VHD],    g_at_l[NT*NH*VHD];

// ------------------------------------------------------------------
// PTX helpers (sm_80+ ISA: cp.async / ldmatrix / mma.sync fp16)
// ------------------------------------------------------------------
__device__ __forceinline__ uint32_t smem_u32(const void* p) {
    uint32_t a;
    asm("{ .reg .u64 t; cvta.to.shared.u64 t, %1; cvt.u32.u64 %0, t; }" : "=r"(a) : "l"(p));
    return a;
}
__device__ __forceinline__ void cp16(uint32_t dst, const void* src) {
    asm volatile("cp.async.cg.shared.global [%0], [%1], 16;" :: "r"(dst), "l"(src));
}
__device__ __forceinline__ void cp_commit() {
    asm volatile("cp.async.commit_group;" ::: "memory");
}
template<int N> __device__ __forceinline__ void cp_wait() {
    asm volatile("cp.async.wait_group %0;" :: "n"(N) : "memory");
}
__device__ __forceinline__ void ldm4(uint32_t* r, uint32_t addr) {
    asm volatile("ldmatrix.sync.aligned.m8n8.x4.shared.b16 {%0,%1,%2,%3}, [%4];"
        : "=r"(r[0]), "=r"(r[1]), "=r"(r[2]), "=r"(r[3]) : "r"(addr));
}
__device__ __forceinline__ void mma_f16(float* c, const uint32_t* a, uint32_t b0, uint32_t b1) {
    asm volatile(
        "mma.sync.aligned.m16n8k16.row.col.f32.f16.f16.f32 "
        "{%0,%1,%2,%3}, {%4,%5,%6,%7}, {%8,%9}, {%0,%1,%2,%3};"
        : "+f"(c[0]), "+f"(c[1]), "+f"(c[2]), "+f"(c[3])
        : "r"(a[0]), "r"(a[1]), "r"(a[2]), "r"(a[3]), "r"(b0), "r"(b1));
}

// ------------------------------------------------------------------
// fp16 2-term split GEMM: C[m][n] = sum_k (Ah+Al)[m][k]*B[n][k]
// tile 128x128, BK=32, 256 threads (2x4 warps, 64x32 warp tile),
// 4-stage cp.async pipeline, padded smem stride 40 h16 (80 B).
// mode 0: C = acc + bias (float out, ldc=Nw, store-guard n<Nw)
// mode 1: scores: acc*SCALE + mask  (z = bh)
// mode 2: PV: split to Oh/Ol with head scatter (z = bh)
// ------------------------------------------------------------------
#define LDSX 40
#define TSZ  (128*LDSX)          /* elems per tile (5120) */
#define STGB (3*TSZ*2)           /* bytes per stage (30720): Ah, Al, B */
#define NSTG 4
#define SMEM_BYTES (NSTG*STGB)   /* 122880 bytes */

__global__ void __launch_bounds__(256, 1)
k_mma(const h16* __restrict__ Ah, const h16* __restrict__ Al,
      const h16* __restrict__ B,
      float* __restrict__ C, const float* __restrict__ bias,
      const float* __restrict__ mask,
      h16* __restrict__ Oh, h16* __restrict__ Ol,
      int M, int N, int K, int Nw, int mode)
{
    extern __shared__ h16 sm[];
    const uint32_t sb = smem_u32(sm);

    const int tid  = threadIdx.x;
    const int wid  = tid >> 5, lane = tid & 31;
    const int wm   = (wid & 1) * 64;      // warp M offset in tile
    const int wn   = (wid >> 1) * 32;     // warp N offset in tile
    const int z    = blockIdx.z;
    const int m0   = blockIdx.y * 128, n0 = blockIdx.x * 128;

    if (mode == 1) {
        Ah += (u64)z*SS*QKD; Al += (u64)z*SS*QKD;
        B  += (u64)z*SS*QKD;
        C  += (u64)z*SS*SS;
    } else if (mode == 2) {
        Ah += (u64)z*SS*SS;  Al += (u64)z*SS*SS;
        B  += (u64)z*VHD*SS;
    }

    const u64 aoff0 = (u64)m0 * K;
    const u64 boff0 = (u64)n0 * K;
    const int NC = K >> 5;

    // async fill of one stage: 3 tiles x 128 rows x 32 h16 (4x16B/row)
    auto fill = [&](int stage, int c) {
        const uint32_t sbase = sb + stage * STGB;
        const u64 ka = aoff0 + c * 32;
        const u64 kb = boff0 + c * 32;
#pragma unroll
        for (int j = 0; j < 6; ++j) {
            const int i   = tid + j * 256;
            const int t   = i >> 9;                  // 0:Ah 1:Al 2:B
            const int row = (i >> 2) & 127;
            const int ch  = i & 3;
            const h16* g  = (t == 0) ? Ah : (t == 1) ? Al : B;
            const u64 base = (t < 2) ? ka : kb;
            const uint32_t dst = sbase + (t * TSZ + row * LDSX + ch * 8) * 2;
            cp16(dst, g + base + (u64)row * K + ch * 8);
        }
    };

    float acc[4][4][4];
#pragma unroll
    for (int a = 0; a < 4; ++a)
#pragma unroll
        for (int b = 0; b < 4; ++b)
#pragma unroll
            for (int d = 0; d < 4; ++d) acc[a][b][d] = 0.f;

    // prologue: fill first 3 stages
#pragma unroll
    for (int p = 0; p < NSTG - 1; ++p) {
        if (p < NC) fill(p, p);
        cp_commit();
    }

    // ldmatrix lane addressing
    const int a_row = lane & 15;
    const int a_kof = (lane >> 4) * 8;
    const int b_row = (lane & 7) + ((lane >> 4) & 1) * 8;
    const int b_kof = ((lane >> 3) & 1) * 8;

    for (int c = 0; c < NC; ++c) {
        cp_wait<NSTG - 2>();
        __syncthreads();
        if (c + NSTG - 1 < NC) fill((c + NSTG - 1) & (NSTG - 1), c + NSTG - 1);
        cp_commit();

        const uint32_t st = sb + (c & (NSTG - 1)) * STGB;
#pragma unroll
        for (int ks = 0; ks < 2; ++ks) {
            const int k0s = ks * 16;
            uint32_t aH[4][4], aL[4][4], bS[2][4];
#pragma unroll
            for (int mi = 0; mi < 4; ++mi) {
                const uint32_t ra = st + ((wm + mi * 16 + a_row) * LDSX + k0s + a_kof) * 2;
                ldm4(aH[mi], ra);
                ldm4(aL[mi], ra + TSZ * 2);
            }
#pragma unroll
            for (int np = 0; np < 2; ++np) {
                const uint32_t rb = st + (2 * TSZ + (wn + np * 16 + b_row) * LDSX + k0s + b_kof) * 2;
                ldm4(bS[np], rb);
            }
#pragma unroll
            for (int mi = 0; mi < 4; ++mi) {
#pragma unroll
                for (int ni = 0; ni < 4; ++ni) {
                    const uint32_t b0 = bS[ni >> 1][(ni & 1) * 2];
                    const uint32_t b1 = bS[ni >> 1][(ni & 1) * 2 + 1];
                    mma_f16(acc[mi][ni], aH[mi], b0, b1);
                    mma_f16(acc[mi][ni], aL[mi], b0, b1);
                }
            }
        }
    }

    // ---- epilogue
    const int er = lane >> 2;
    const int ec = (lane & 3) * 2;
#pragma unroll
    for (int mi = 0; mi < 4; ++mi) {
#pragma unroll
        for (int ni = 0; ni < 4; ++ni) {
            const int m = m0 + wm + mi * 16 + er;
            const int n = n0 + wn + ni * 8 + ec;
            const float* ac = acc[mi][ni];
            if (mode == 0) {
                if (n < Nw) {
                    const float b0 = bias[n], b1 = bias[n + 1];
                    float2 o0 = make_float2(ac[0] + b0, ac[1] + b1);
                    float2 o1 = make_float2(ac[2] + b0, ac[3] + b1);
                    *(float2*)&C[(u64)m * Nw + n]       = o0;
                    *(float2*)&C[(u64)(m + 8) * Nw + n] = o1;
                }
            } else if (mode == 1) {
                float2 mk0 = *(const float2*)&mask[(u64)m * SS + n];
                float2 mk1 = *(const float2*)&mask[(u64)(m + 8) * SS + n];
                float2 o0 = make_float2(ac[0] * SCALE + mk0.x, ac[1] * SCALE + mk0.y);
                float2 o1 = make_float2(ac[2] * SCALE + mk1.x, ac[3] * SCALE + mk1.y);
                *(float2*)&C[(u64)m * SS + n]       = o0;
                *(float2*)&C[(u64)(m + 8) * SS + n] = o1;
            } else {
                const int b = z >> 4, h = z & 15;
                const u64 r0o = (u64)(b * SS + m)     * (NH * VHD) + (u64)h * VHD + n;
                const u64 r1o = (u64)(b * SS + m + 8) * (NH * VHD) + (u64)h * VHD + n;
#pragma unroll
                for (int d = 0; d < 2; ++d) {
                    float v0 = ac[d], v1 = ac[2 + d];
                    h16 h0 = __float2half_rn(v0);
                    h16 h1 = __float2half_rn(v1);
                    Oh[r0o + d] = h0; Ol[r0o + d] = __float2half_rn(v0 - __half2float(h0));
                    Oh[r1o + d] = h1; Ol[r1o + d] = __float2half_rn(v1 - __half2float(h1));
                }
            }
        }
    }
}

// ------------------------------------------------------------------
// elementwise kernels
// ------------------------------------------------------------------
__global__ void k_split(const float* __restrict__ x, h16* __restrict__ h,
                        h16* __restrict__ l, int n)
{
    int i = blockIdx.x * 256 + threadIdx.x;
    if (i >= n) return;
    float v = x[i];
    h16 hv = __float2half_rn(v);
    h[i] = hv;
    l[i] = __float2half_rn(v - __half2float(hv));
}

__global__ void k_split1(const float* __restrict__ x, h16* __restrict__ o, int n)
{
    int i = blockIdx.x * 256 + threadIdx.x;
    if (i >= n) return;
    o[i] = __float2half_rn(x[i]);
}

__global__ void k_split1_pad(const float* __restrict__ x, h16* __restrict__ o,
                             int rows_src, int cols, int rows_dst)
{
    int i = blockIdx.x * 256 + threadIdx.x;
    if (i >= rows_dst * cols) return;
    int r = i / cols;
    o[i] = __float2half_rn((r < rows_src) ? x[i] : 0.f);
}

__global__ void __launch_bounds__(256)
k_rmsnorm(const float* __restrict__ X, const float* __restrict__ w,
          h16* __restrict__ Yh, h16* __restrict__ Yl,
          int W, int inStride, int outStride)
{
    int row = blockIdx.x;
    const float* x = X + (u64)row * inStride;
    float s = 0.f;
    for (int i = threadIdx.x; i < W; i += 256) { float v = x[i]; s += v * v; }
    __shared__ float red[256];
    red[threadIdx.x] = s; __syncthreads();
    for (int off = 128; off > 0; off >>= 1) {
        if (threadIdx.x < off) red[threadIdx.x] += red[threadIdx.x + off];
        __syncthreads();
    }
    float r = rsqrtf(red[0] / (float)W + 1e-6f);
    h16* yh = Yh + (u64)row * outStride;
    h16* yl = Yl + (u64)row * outStride;
    for (int i = threadIdx.x; i < W; i += 256) {
        float v = w[i] * (x[i] * r);
        h16 hv = __float2half_rn(v);
        yh[i] = hv;
        yl[i] = __float2half_rn(v - __half2float(hv));
    }
}

__device__ __forceinline__ float rope_val(float x1, float x2, int s, int i, int odd)
{
    float inv = powf(10000.f, -(float)(2 * i) / (float)ROPEd);
    float sn, cs;
    sincosf((float)s * inv, &sn, &cs);
    return odd ? (x1 * sn + x2 * cs) : (x1 * cs - x2 * sn);
}
__device__ __forceinline__ void wr_split(h16* H, h16* L, u64 o, float v)
{
    h16 hv = __float2half_rn(v);
    H[o] = hv;
    L[o] = __float2half_rn(v - __half2float(hv));
}

__global__ void k_prep_q()
{
    int idx = blockIdx.x * blockDim.x + threadIdx.x;
    if (idx >= BB * SS * NH * QKD) return;
    int d = idx % QKD;
    int h = (idx / QKD) % NH;
    int s = (idx / (QKD * NH)) % SS;
    int b =  idx / (QKD * NH * SS);
    const float* qrow = g_q + (u64)(b * SS + s) * HID + h * QKD;
    float val;
    if (d < NOPEd) val = qrow[d];
    else {
        int i = (d - NOPEd) >> 1;
        val = rope_val(qrow[NOPEd + 2 * i], qrow[NOPEd + 2 * i + 1], s, i, (d - NOPEd) & 1);
    }
    wr_split(g_Qh_h, g_Qh_l, ((u64)(b * NH + h) * SS + s) * QKD + d, val);
}

__global__ void k_prep_k()
{
    int idx = blockIdx.x * blockDim.x + threadIdx.x;
    if (idx >= BB * SS * NH * QKD) return;
    int d = idx % QKD;
    int h = (idx / QKD) % NH;
    int s = (idx / (QKD * NH)) % SS;
    int b =  idx / (QKD * NH * SS);
    float val;
    if (d < NOPEd) {
        val = g_kvb[(u64)(b * SS + s) * (NH * KVOUT) + h * KVOUT + d];
    } else {
        int i = (d - NOPEd) >> 1;
        const float* kr = g_kv + (u64)(b * SS + s) * KVA_N + KVL;
        val = rope_val(kr[2 * i], kr[2 * i + 1], s, i, (d - NOPEd) & 1);
    }
    g_Kh[((u64)(b * NH + h) * SS + s) * QKD + d] = __float2half_rn(val);
}

__global__ void k_prep_v()   // V transposed: [b][h][d][t], single fp16
{
    int idx = blockIdx.x * blockDim.x + threadIdx.x;
    if (idx >= BB * NH * VHD * SS) return;
    int s = idx % SS;
    int d = (idx / SS) % VHD;
    int h = (idx / (SS * VHD)) % NH;
    int b =  idx / (SS * VHD * NH);
    float v = g_kvb[(u64)(b * SS + s) * (NH * KVOUT) + h * KVOUT + NOPEd + d];
    g_Vt[idx] = __float2half_rn(v);
}

__global__ void __launch_bounds__(256)
k_softmax()
{
    const float* p = g_sc + (u64)blockIdx.x * SS;
    int t = threadIdx.x;
    float4 v = *(const float4*)&p[t * 4];
    __shared__ float red[256];
    float mx = fmaxf(fmaxf(v.x, v.y), fmaxf(v.z, v.w));
    red[t] = mx; __syncthreads();
    for (int off = 128; off > 0; off >>= 1) {
        if (t < off) red[t] = fmaxf(red[t], red[t + off]);
        __syncthreads();
    }
    mx = red[0]; __syncthreads();
    v.x = expf(v.x - mx); v.y = expf(v.y - mx);
    v.z = expf(v.z - mx); v.w = expf(v.w - mx);
    red[t] = v.x + v.y + v.z + v.w; __syncthreads();
    for (int off = 128; off > 0; off >>= 1) {
        if (t < off) red[t] += red[t + off];
        __syncthreads();
    }
    float inv = 1.0f / red[0];
    u64 o = (u64)blockIdx.x * SS + t * 4;
    wr_split(g_P_h, g_P_l, o + 0, v.x * inv);
    wr_split(g_P_h, g_P_l, o + 1, v.y * inv);
    wr_split(g_P_h, g_P_l, o + 2, v.z * inv);
    wr_split(g_P_h, g_P_l, o + 3, v.w * inv);
}

// ------------------------------------------------------------------
// launch
// ------------------------------------------------------------------
static inline void* sym(const void* s) { void* p; cudaGetSymbolAddress(&p, s); return p; }

extern "C" void kernel_launch(void* const* d_in, const int* in_sizes, int n_in,
                              void* d_out, int out_size)
{
    const float* hs        = (const float*)d_in[0];
    const float* mask      = (const float*)d_in[1];
    const float* wq_a_w    = (const float*)d_in[2];
    const float* wq_a_b    = (const float*)d_in[3];
    const float* q_norm_w  = (const float*)d_in[4];
    const float* wq_b_w    = (const float*)d_in[5];
    const float* wq_b_b    = (const float*)d_in[6];
    const float* wkv_a_w   = (const float*)d_in[7];
    const float* wkv_a_b   = (const float*)d_in[8];
    const float* kv_norm_w = (const float*)d_in[9];
    const float* wkv_b_w   = (const float*)d_in[10];
    const float* wkv_b_b   = (const float*)d_in[11];
    const float* wo_w      = (const float*)d_in[12];
    const float* wo_b      = (const float*)d_in[13];
    float* out = (float*)d_out;

    static int smem_set = 0;
    if (!smem_set) {
        cudaFuncSetAttribute(k_mma, cudaFuncAttributeMaxDynamicSharedMemorySize, SMEM_BYTES);
        smem_set = 1;
    }

    h16 *hs_h=(h16*)sym(g_hs_h), *hs_l=(h16*)sym(g_hs_l);
    h16 *wqa=(h16*)sym(g_wqa), *wqb=(h16*)sym(g_wqb);
    h16 *wkva=(h16*)sym(g_wkva), *wkvb=(h16*)sym(g_wkvb), *wo=(h16*)sym(g_wo);
    float *qlat=(float*)sym(g_qlat), *q=(float*)sym(g_q);
    h16 *qln_h=(h16*)sym(g_qln_h), *qln_l=(h16*)sym(g_qln_l);
    float *kv=(float*)sym(g_kv), *kvb=(float*)sym(g_kvb);
    h16 *kvln_h=(h16*)sym(g_kvln_h), *kvln_l=(h16*)sym(g_kvln_l);
    h16 *Qh_h=(h16*)sym(g_Qh_h), *Qh_l=(h16*)sym(g_Qh_l);
    h16 *Kh=(h16*)sym(g_Kh), *Vt=(h16*)sym(g_Vt);
    float *sc=(float*)sym(g_sc);
    h16 *P_h=(h16*)sym(g_P_h), *P_l=(h16*)sym(g_P_l);
    h16 *at_h=(h16*)sym(g_at_h), *at_l=(h16*)sym(g_at_l);

    // ---- splits of inputs/weights
    k_split <<<(NT*HID + 255)/256, 256>>>(hs, hs_h, hs_l, NT*HID);
    k_split1<<<(QL*HID + 255)/256, 256>>>(wq_a_w, wqa, QL*HID);
    k_split1<<<(HID*QL + 255)/256, 256>>>(wq_b_w, wqb, HID*QL);
    k_split1_pad<<<(KVA_NP*HID + 255)/256, 256>>>(wkv_a_w, wkva, KVA_N, HID, KVA_NP);
    k_split1<<<(NH*KVOUT*KVL + 255)/256, 256>>>(wkv_b_w, wkvb, NH*KVOUT*KVL);
    k_split1<<<(HID*NH*VHD + 255)/256, 256>>>(wo_w, wo, HID*NH*VHD);

    // ---- q path
    k_mma<<<dim3(QL/128, NT/128, 1), 256, SMEM_BYTES>>>(
        hs_h, hs_l, wqa, qlat, wq_a_b, nullptr, nullptr, nullptr,
        NT, QL, HID, QL, 0);
    k_rmsnorm<<<NT, 256>>>(qlat, q_norm_w, qln_h, qln_l, QL, QL, QL);
    k_mma<<<dim3(HID/128, NT/128, 1), 256, SMEM_BYTES>>>(
        qln_h, qln_l, wqb, q, wq_b_b, nullptr, nullptr, nullptr,
        NT, HID, QL, HID, 0);

    // ---- kv path
    k_mma<<<dim3(KVA_NP/128, NT/128, 1), 256, SMEM_BYTES>>>(
        hs_h, hs_l, wkva, kv, wkv_a_b, nullptr, nullptr, nullptr,
        NT, KVA_NP, HID, KVA_N, 0);
    k_rmsnorm<<<NT, 256>>>(kv, kv_norm_w, kvln_h, kvln_l, KVL, KVA_N, KVL);
    k_mma<<<dim3(NH*KVOUT/128, NT/128, 1), 256, SMEM_BYTES>>>(
        kvln_h, kvln_l, wkvb, kvb, wkv_b_b, nullptr, nullptr, nullptr,
        NT, NH*KVOUT, KVL, NH*KVOUT, 0);

    // ---- head gather + rope + transpose
    k_prep_q<<<(BB*SS*NH*QKD + 255)/256, 256>>>();
    k_prep_k<<<(BB*SS*NH*QKD + 255)/256, 256>>>();
    k_prep_v<<<(BB*NH*VHD*SS + 255)/256, 256>>>();

    // ---- attention
    k_mma<<<dim3(SS/128, SS/128, BB*NH), 256, SMEM_BYTES>>>(
        Qh_h, Qh_l, Kh, sc, nullptr, mask, nullptr, nullptr,
        SS, SS, QKD, SS, 1);
    k_softmax<<<BB*NH*SS, 256>>>();
    k_mma<<<dim3(VHD/128, SS/128, BB*NH), 256, SMEM_BYTES>>>(
        P_h, P_l, Vt, nullptr, nullptr, nullptr, at_h, at_l,
        SS, VHD, SS, VHD, 2);

    // ---- output projection
    k_mma<<<dim3(HID/128, NT/128, 1), 256, SMEM_BYTES>>>(
        at_h, at_l, wo, out, wo_b, nullptr, nullptr, nullptr,
        NT, HID, NH*VHD, HID, 0);
}